// round 16
// baseline (speedup 1.0000x reference)
#include <cuda_runtime.h>
#include <cuda_bf16.h>
#include <cstdint>

#define NB 2
#define TT 4096
#define DM 768
#define NH 12
#define DH 64
#define MROWS (NB * TT)   // 8192

typedef uint32_t u32;
typedef __nv_bfloat16 bf16;
typedef __nv_bfloat162 bf162;

#define QSCALE 0.18033688011112042f   // 0.125 * log2(e)

// ---------------------------------------------------------------------------
// Scratch in __device__ globals (allocation-free rule)
// ---------------------------------------------------------------------------
__device__ bf16 g_xh[(size_t)MROWS * DM];
__device__ bf16 g_xl[(size_t)MROWS * DM];
__device__ bf16 g_wqh[(size_t)DM * DM];
__device__ bf16 g_wql[(size_t)DM * DM];
__device__ bf16 g_wkh[(size_t)DM * DM];
__device__ bf16 g_wkl[(size_t)DM * DM];
__device__ bf16 g_wvh[(size_t)DM * DM];
__device__ bf16 g_wvl[(size_t)DM * DM];
__device__ bf16 g_woh[(size_t)DM * DM];
__device__ bf16 g_wol[(size_t)DM * DM];
__device__ float g_qf[(size_t)MROWS * DM];   // tf32-formatted fp32
__device__ float g_kf[(size_t)MROWS * DM];   // tf32-formatted fp32
__device__ float g_vf[(size_t)MROWS * DM];   // tf32-formatted fp32
__device__ bf16 g_ah[(size_t)MROWS * DM];
__device__ bf16 g_al[(size_t)MROWS * DM];
__device__ float g_maskf[(size_t)NB * TT];   // t-domain: 0 or -1e30*log2e
__device__ int   g_act[NB * 64];             // 0=skip, 1=partial, 2=full
__device__ int   g_na[NB];                   // last active tile + 1

// ---------------------------------------------------------------------------
// Helpers
// ---------------------------------------------------------------------------
__device__ __forceinline__ u32 s2u(const void* p) {
    return (u32)__cvta_generic_to_shared(p);
}
__device__ __forceinline__ void cpa16(u32 dst, const void* src) {
    asm volatile("cp.async.cg.shared.global [%0], [%1], 16;" :: "r"(dst), "l"(src));
}
#define CP_COMMIT()  asm volatile("cp.async.commit_group;")
#define CP_WAIT(N)   asm volatile("cp.async.wait_group %0;" :: "n"(N))

__device__ __forceinline__ void ldsm4(u32& r0, u32& r1, u32& r2, u32& r3, u32 a) {
    asm volatile("ldmatrix.sync.aligned.m8n8.x4.shared.b16 {%0,%1,%2,%3},[%4];"
                 : "=r"(r0), "=r"(r1), "=r"(r2), "=r"(r3) : "r"(a));
}
__device__ __forceinline__ void mma16816(float* c, u32 a0, u32 a1, u32 a2, u32 a3,
                                         u32 b0, u32 b1) {
    asm volatile(
        "mma.sync.aligned.m16n8k16.row.col.f32.bf16.bf16.f32 "
        "{%0,%1,%2,%3},{%4,%5,%6,%7},{%8,%9},{%0,%1,%2,%3};"
        : "+f"(c[0]), "+f"(c[1]), "+f"(c[2]), "+f"(c[3])
        : "r"(a0), "r"(a1), "r"(a2), "r"(a3), "r"(b0), "r"(b1));
}
__device__ __forceinline__ void mma1688t(float* c, u32 a0, u32 a1, u32 a2, u32 a3,
                                         u32 b0, u32 b1) {
    asm volatile(
        "mma.sync.aligned.m16n8k8.row.col.f32.tf32.tf32.f32 "
        "{%0,%1,%2,%3},{%4,%5,%6,%7},{%8,%9},{%0,%1,%2,%3};"
        : "+f"(c[0]), "+f"(c[1]), "+f"(c[2]), "+f"(c[3])
        : "r"(a0), "r"(a1), "r"(a2), "r"(a3), "r"(b0), "r"(b1));
}
__device__ __forceinline__ u32 lds32(u32 a) {
    u32 v;
    asm volatile("ld.shared.b32 %0,[%1];" : "=r"(v) : "r"(a));
    return v;
}
__device__ __forceinline__ u32 cvt_tf32(float f) {
    u32 u;
    asm("cvt.rna.tf32.f32 %0, %1;" : "=r"(u) : "f"(f));
    return u;
}
__device__ __forceinline__ float ex2(float x) {
    float y;
    asm("ex2.approx.ftz.f32 %0, %1;" : "=f"(y) : "f"(x));
    return y;
}
// bf16 tile swizzle (128B rows, 8 chunks)
__device__ __forceinline__ u32 swz(int row, int chunk) {
    return (u32)(row * 128 + ((chunk ^ (row & 7)) << 4));
}
__device__ __forceinline__ u32 frag_addr(u32 base, int r0, int c0, int lane) {
    return base + swz(r0 + (lane & 15), c0 + (lane >> 4));
}
// fp32 tile swizzle (256B rows, 16 chunks): chunk ^= (row&7)*2
__device__ __forceinline__ u32 swzf_chunk(int row, int chunk) {
    return (u32)(row * 256 + ((chunk ^ ((row & 7) << 1)) << 4));
}

// ---------------------------------------------------------------------------
// Mask prep
// ---------------------------------------------------------------------------
__global__ void prep_mask_kernel(const int* __restrict__ mask,
                                 float* __restrict__ out,
                                 int* __restrict__ actg, int* __restrict__ nag) {
    __shared__ int s_any[64];
    const int n = blockIdx.x, t = threadIdx.x;
    bool any = false, all = true;
#pragma unroll 8
    for (int j = 0; j < 64; j++) {
        int m = mask[n * TT + t * 64 + j];
        out[n * TT + t * 64 + j] = m ? -1.4426950e30f : 0.0f;
        any |= (m == 0);
        all &= (m == 0);
    }
    actg[n * 64 + t] = any ? (all ? 2 : 1) : 0;
    s_any[t] = any ? 1 : 0;
    __syncthreads();
    if (t == 0) {
        int na = 0;
        for (int j = 0; j < 64; j++)
            if (s_any[j]) na = j + 1;
        nag[n] = na;
    }
}

// ---------------------------------------------------------------------------
// fp32 -> bf16 hi/lo split
// ---------------------------------------------------------------------------
__device__ __forceinline__ void split4(float4 v, uint2& h, uint2& l) {
    bf162 h01 = __floats2bfloat162_rn(v.x, v.y);
    bf162 h23 = __floats2bfloat162_rn(v.z, v.w);
    float2 f01 = __bfloat1622float2(h01);
    float2 f23 = __bfloat1622float2(h23);
    bf162 l01 = __floats2bfloat162_rn(v.x - f01.x, v.y - f01.y);
    bf162 l23 = __floats2bfloat162_rn(v.z - f23.x, v.w - f23.y);
    h = make_uint2(*(u32*)&h01, *(u32*)&h23);
    l = make_uint2(*(u32*)&l01, *(u32*)&l23);
}

__global__ void split_kernel(const float* __restrict__ in, bf16* __restrict__ h,
                             bf16* __restrict__ l, int n4) {
    int i = blockIdx.x * blockDim.x + threadIdx.x;
    if (i >= n4) return;
    uint2 hh, ll;
    split4(reinterpret_cast<const float4*>(in)[i], hh, ll);
    reinterpret_cast<uint2*>(h)[i] = hh;
    reinterpret_cast<uint2*>(l)[i] = ll;
}

__global__ void split4w_kernel(const float* __restrict__ W0, const float* __restrict__ W1,
                               const float* __restrict__ W2, const float* __restrict__ W3,
                               bf16* __restrict__ h0, bf16* __restrict__ l0,
                               bf16* __restrict__ h1, bf16* __restrict__ l1,
                               bf16* __restrict__ h2, bf16* __restrict__ l2,
                               bf16* __restrict__ h3, bf16* __restrict__ l3, int n4) {
    int i = blockIdx.x * blockDim.x + threadIdx.x;
    int w = i / n4, j = i - w * n4;
    if (w >= 4) return;
    const float* in = (w == 0) ? W0 : (w == 1) ? W1 : (w == 2) ? W2 : W3;
    bf16* h = (w == 0) ? h0 : (w == 1) ? h1 : (w == 2) ? h2 : h3;
    bf16* l = (w == 0) ? l0 : (w == 1) ? l1 : (w == 2) ? l2 : l3;
    uint2 hh, ll;
    split4(reinterpret_cast<const float4*>(in)[j], hh, ll);
    reinterpret_cast<uint2*>(h)[j] = hh;
    reinterpret_cast<uint2*>(l)[j] = ll;
}

// ---------------------------------------------------------------------------
// 128x128 GEMM mainloop (bf16x3, 3-stage cp.async, BK=32). Used by qkv.
// ---------------------------------------------------------------------------
struct GemmCore {
    float acc[4][4][4];

    __device__ __forceinline__ void run(char* smraw, int tid, int lane,
                                        int wm, int wn, int row0, int col0,
                                        const bf16* Ah, const bf16* Al,
                                        const bf16* Bh, const bf16* Bl) {
#pragma unroll
        for (int a = 0; a < 4; a++)
#pragma unroll
            for (int b = 0; b < 4; b++)
#pragma unroll
                for (int c = 0; c < 4; c++) acc[a][b][c] = 0.0f;

        auto load_stage = [&](int s) {
            char* base = smraw + (s % 3) * 32768;
            u32 ab = s2u(base), bb = ab + 16384;
            int k0 = s * 32;
#pragma unroll
            for (int i = tid; i < 1024; i += 256) {
                int r = i >> 3, c = i & 7;
                const bf16* asrc = (c < 4)
                    ? &Ah[(size_t)(row0 + r) * DM + k0 + c * 8]
                    : &Al[(size_t)(row0 + r) * DM + k0 + (c - 4) * 8];
                cpa16(ab + swz(r, c), asrc);
                const bf16* bsrc = (c < 4)
                    ? &Bh[(size_t)(col0 + r) * DM + k0 + c * 8]
                    : &Bl[(size_t)(col0 + r) * DM + k0 + (c - 4) * 8];
                cpa16(bb + swz(r, c), bsrc);
            }
        };

        load_stage(0); CP_COMMIT();
        load_stage(1); CP_COMMIT();

        const int NS = DM / 32;  // 24
#pragma unroll 1
        for (int s = 0; s < NS; s++) {
            if (s + 1 < NS) { CP_WAIT(1); } else { CP_WAIT(0); }
            __syncthreads();

            u32 ab = s2u(smraw + (s % 3) * 32768), bb = ab + 16384;
#pragma unroll
            for (int kt = 0; kt < 2; kt++) {
                const int ch = 2 * kt, cl = 4 + 2 * kt;
                u32 bhf[4][2], blf[4][2];
#pragma unroll
                for (int half = 0; half < 2; half++) {
                    u32 r0, r1, r2, r3;
                    ldsm4(r0, r1, r2, r3, frag_addr(bb, wn * 32 + half * 16, ch, lane));
                    bhf[2 * half][0] = r0; bhf[2 * half + 1][0] = r1;
                    bhf[2 * half][1] = r2; bhf[2 * half + 1][1] = r3;
                    ldsm4(r0, r1, r2, r3, frag_addr(bb, wn * 32 + half * 16, cl, lane));
                    blf[2 * half][0] = r0; blf[2 * half + 1][0] = r1;
                    blf[2 * half][1] = r2; blf[2 * half + 1][1] = r3;
                }
#pragma unroll
                for (int mt = 0; mt < 4; mt++) {
                    u32 ah4[4], al4[4];
                    ldsm4(ah4[0], ah4[1], ah4[2], ah4[3],
                          frag_addr(ab, wm * 64 + mt * 16, ch, lane));
                    ldsm4(al4[0], al4[1], al4[2], al4[3],
                          frag_addr(ab, wm * 64 + mt * 16, cl, lane));
#pragma unroll
                    for (int nt = 0; nt < 4; nt++) {
                        mma16816(acc[mt][nt], ah4[0], ah4[1], ah4[2], ah4[3],
                                 bhf[nt][0], bhf[nt][1]);
                        mma16816(acc[mt][nt], ah4[0], ah4[1], ah4[2], ah4[3],
                                 blf[nt][0], blf[nt][1]);
                        mma16816(acc[mt][nt], al4[0], al4[1], al4[2], al4[3],
                                 bhf[nt][0], bhf[nt][1]);
                    }
                }
            }
            if (s + 2 < NS) { load_stage(s + 2); CP_COMMIT(); }
        }
    }
};

// ---------------------------------------------------------------------------
// Fused Q/K/V projection: epilogue emits tf32-formatted fp32, head-split.
// ---------------------------------------------------------------------------
__global__ __launch_bounds__(256, 2)
void gemm_qkv_kernel(const bf16* __restrict__ Xh, const bf16* __restrict__ Xl,
                     const bf16* __restrict__ Wqh, const bf16* __restrict__ Wql,
                     const bf16* __restrict__ Wkh, const bf16* __restrict__ Wkl,
                     const bf16* __restrict__ Wvh, const bf16* __restrict__ Wvl,
                     const float* __restrict__ bq, const float* __restrict__ bk,
                     const float* __restrict__ bv,
                     float* __restrict__ Qf, float* __restrict__ Kf,
                     float* __restrict__ Vf) {
    extern __shared__ char smraw[];
    const int tid = threadIdx.x, lane = tid & 31, wid = tid >> 5;
    const int wm = wid >> 2, wn = wid & 3;
    const int row0 = blockIdx.x * 128, col0 = blockIdx.y * 128;
    const int w = blockIdx.z;

    const bf16* Bh = (w == 0) ? Wqh : (w == 1) ? Wkh : Wvh;
    const bf16* Bl = (w == 0) ? Wql : (w == 1) ? Wkl : Wvl;
    const float* bias = (w == 0) ? bq : (w == 1) ? bk : bv;
    float* Of = (w == 0) ? Qf : (w == 1) ? Kf : Vf;
    const float cscale = (w == 0) ? QSCALE : 1.0f;

    GemmCore core;
    core.run(smraw, tid, lane, wm, wn, row0, col0, Xh, Xl, Bh, Bl);

    const int g = lane >> 2, t4 = lane & 3;
#pragma unroll
    for (int mt = 0; mt < 4; mt++)
#pragma unroll
        for (int nt = 0; nt < 4; nt++) {
            int col = col0 + wn * 32 + nt * 8 + t4 * 2;
            float bv0 = bias[col], bv1 = bias[col + 1];
#pragma unroll
            for (int half = 0; half < 2; half++) {
                int row = row0 + wm * 64 + mt * 16 + g + half * 8;
                float c0 = (core.acc[mt][nt][2 * half] + bv0) * cscale;
                float c1 = (core.acc[mt][nt][2 * half + 1] + bv1) * cscale;
                int n = row >> 12, t = row & (TT - 1);
                int h = col >> 6, d = col & 63;
                size_t idx = (((size_t)(n * NH + h)) * TT + t) * DH + d;
                *reinterpret_cast<uint2*>(&Of[idx]) =
                    make_uint2(cvt_tf32(c0), cvt_tf32(c1));
            }
        }
}

// ---------------------------------------------------------------------------
// Output projection: 64x128 tiles, bf16x3 (unchanged).
// ---------------------------------------------------------------------------
__global__ __launch_bounds__(256, 2)
void gemm_out_kernel(const bf16* __restrict__ Ahg, const bf16* __restrict__ Alg,
                     const bf16* __restrict__ Bh, const bf16* __restrict__ Bl,
                     const float* __restrict__ bias, float* __restrict__ C) {
    extern __shared__ char smraw[];
    const int tid = threadIdx.x, lane = tid & 31, wid = tid >> 5;
    const int wm = wid >> 2, wn = wid & 3;
    const int row0 = blockIdx.x * 64, col0 = blockIdx.y * 128;

    float acc[2][4][4];
#pragma unroll
    for (int a = 0; a < 2; a++)
#pragma unroll
        for (int b = 0; b < 4; b++)
#pragma unroll
            for (int c = 0; c < 4; c++) acc[a][b][c] = 0.0f;

    auto load_stage = [&](int s) {
        char* base = smraw + (s % 3) * 24576;
        u32 ab = s2u(base), bb = ab + 8192;
        int k0 = s * 32;
#pragma unroll
        for (int i = tid; i < 512; i += 256) {
            int r = i >> 3, c = i & 7;
            const bf16* asrc = (c < 4)
                ? &Ahg[(size_t)(row0 + r) * DM + k0 + c * 8]
                : &Alg[(size_t)(row0 + r) * DM + k0 + (c - 4) * 8];
            cpa16(ab + swz(r, c), asrc);
        }
#pragma unroll
        for (int i = tid; i < 1024; i += 256) {
            int r = i >> 3, c = i & 7;
            const bf16* bsrc = (c < 4)
                ? &Bh[(size_t)(col0 + r) * DM + k0 + c * 8]
                : &Bl[(size_t)(col0 + r) * DM + k0 + (c - 4) * 8];
            cpa16(bb + swz(r, c), bsrc);
        }
    };

    load_stage(0); CP_COMMIT();
    load_stage(1); CP_COMMIT();

    const int NS = DM / 32;  // 24
#pragma unroll 1
    for (int s = 0; s < NS; s++) {
        if (s + 1 < NS) { CP_WAIT(1); } else { CP_WAIT(0); }
        __syncthreads();

        u32 ab = s2u(smraw + (s % 3) * 24576), bb = ab + 8192;
#pragma unroll
        for (int kt = 0; kt < 2; kt++) {
            const int ch = 2 * kt, cl = 4 + 2 * kt;
            u32 bhf[4][2], blf[4][2];
#pragma unroll
            for (int half = 0; half < 2; half++) {
                u32 r0, r1, r2, r3;
                ldsm4(r0, r1, r2, r3, frag_addr(bb, wn * 32 + half * 16, ch, lane));
                bhf[2 * half][0] = r0; bhf[2 * half + 1][0] = r1;
                bhf[2 * half][1] = r2; bhf[2 * half + 1][1] = r3;
                ldsm4(r0, r1, r2, r3, frag_addr(bb, wn * 32 + half * 16, cl, lane));
                blf[2 * half][0] = r0; blf[2 * half + 1][0] = r1;
                blf[2 * half][1] = r2; blf[2 * half + 1][1] = r3;
            }
#pragma unroll
            for (int mt = 0; mt < 2; mt++) {
                u32 ah4[4], al4[4];
                ldsm4(ah4[0], ah4[1], ah4[2], ah4[3],
                      frag_addr(ab, wm * 32 + mt * 16, ch, lane));
                ldsm4(al4[0], al4[1], al4[2], al4[3],
                      frag_addr(ab, wm * 32 + mt * 16, cl, lane));
#pragma unroll
                for (int nt = 0; nt < 4; nt++) {
                    mma16816(acc[mt][nt], ah4[0], ah4[1], ah4[2], ah4[3],
                             bhf[nt][0], bhf[nt][1]);
                    mma16816(acc[mt][nt], ah4[0], ah4[1], ah4[2], ah4[3],
                             blf[nt][0], blf[nt][1]);
                    mma16816(acc[mt][nt], al4[0], al4[1], al4[2], al4[3],
                             bhf[nt][0], bhf[nt][1]);
                }
            }
        }
        if (s + 2 < NS) { load_stage(s + 2); CP_COMMIT(); }
    }

    const int g = lane >> 2, t4 = lane & 3;
#pragma unroll
    for (int mt = 0; mt < 2; mt++)
#pragma unroll
        for (int nt = 0; nt < 4; nt++) {
            int col = col0 + wn * 32 + nt * 8 + t4 * 2;
            float bv0 = bias[col], bv1 = bias[col + 1];
#pragma unroll
            for (int half = 0; half < 2; half++) {
                int row = row0 + wm * 32 + mt * 16 + g + half * 8;
                float c0 = acc[mt][nt][2 * half] + bv0;
                float c1 = acc[mt][nt][2 * half + 1] + bv1;
                *reinterpret_cast<float2*>(&C[(size_t)row * DM + col]) =
                    make_float2(c0, c1);
            }
        }
}

// ---------------------------------------------------------------------------
// Flash attention, full tf32 (m16n8k8): S = Q K^T, O += P V.
// All tiles fp32 (tf32-formatted), chunk-swizzle chunk^((row&7)*2).
// smem: Q 32KB | 2 KV stages of (K 16KB + V 16KB) = 96KB.
// Per tile kb: CP_WAIT(1)[K ready] -> bar -> issue K/V(kb+1) -> S + softmax
// -> CP_WAIT(2)[V ready] -> bar -> PV.
// Fragment layouts (m16n8k8 .row.col, lane = 4g + t4):
//   A: a0=[g][t4] a1=[g+8][t4] a2=[g][t4+4] a3=[g+8][t4+4]
//   B: b0=[k=t4][n=g] b1=[k=t4+4][n=g]
//   C: c0=[g][2t4] c1=[g][2t4+1] c2=[g+8][2t4] c3=[g+8][2t4+1]
// ---------------------------------------------------------------------------
__global__ __launch_bounds__(256, 2)
void flash_tf32_kernel(const float* __restrict__ Qg, const float* __restrict__ Kg,
                       const float* __restrict__ Vg,
                       const float* __restrict__ mbf,
                       const int* __restrict__ actg, const int* __restrict__ nag,
                       bf16* __restrict__ Aho, bf16* __restrict__ Alo) {
    extern __shared__ char smraw[];
    __shared__ int act_s[64];
    const u32 QB = s2u(smraw);

    const int n = blockIdx.z, h = blockIdx.y;
    const int q0 = blockIdx.x * 128;
    const size_t hb = ((size_t)(n * NH + h)) * TT * DH;
    const float* mb = mbf + (size_t)n * TT;

    const int tid = threadIdx.x, lane = tid & 31, wid = tid >> 5;
    const int g = lane >> 2, t4 = lane & 3;
    const int w16 = wid * 16;
    const int gx = g << 1;                 // (row&7)<<1 for rows == g pattern

    // Stage Q (fp32): 128 rows x 16 chunks
#pragma unroll
    for (int i = tid; i < 2048; i += 256) {
        int r = i >> 4, ch = i & 15;
        cpa16(QB + swzf_chunk(r, ch), Qg + hb + (size_t)(q0 + r) * DH + ch * 4);
    }
    CP_COMMIT();

    if (tid < 64) act_s[tid] = actg[n * 64 + tid];
    const int na = nag[n];
    __syncthreads();

    auto load_k = [&](int kb) {
        u32 base = s2u(smraw + 32768 + (kb & 1) * 32768);
        int c0 = kb * 64;
#pragma unroll
        for (int i = tid; i < 1024; i += 256) {
            int r = i >> 4, ch = i & 15;
            cpa16(base + swzf_chunk(r, ch),
                  Kg + hb + (size_t)(c0 + r) * DH + ch * 4);
        }
    };
    auto load_v = [&](int kb) {
        u32 base = s2u(smraw + 32768 + (kb & 1) * 32768) + 16384;
        int c0 = kb * 64;
#pragma unroll
        for (int i = tid; i < 1024; i += 256) {
            int r = i >> 4, ch = i & 15;
            cpa16(base + swzf_chunk(r, ch),
                  Vg + hb + (size_t)(c0 + r) * DH + ch * 4);
        }
    };

    float oacc[8][4];
#pragma unroll
    for (int a = 0; a < 8; a++)
#pragma unroll
        for (int b = 0; b < 4; b++) oacc[a][b] = 0.0f;
    float mrow0 = -1e30f, mrow1 = -1e30f, lrow0 = 0.0f, lrow1 = 0.0f;

    if (na > 0) {
        load_k(0); CP_COMMIT();
        load_v(0); CP_COMMIT();
    }

#pragma unroll 1
    for (int kb = 0; kb < na; kb++) {
        const bool more = (kb + 1 < na);
        const int af = act_s[kb];
        const int c0 = kb * 64;
        const u32 KB = s2u(smraw + 32768 + (kb & 1) * 32768);
        const u32 VB = KB + 16384;

        // ---- wait for K(kb); barrier also guards buffer reuse ----
        CP_WAIT(1);
        __syncthreads();

        if (more) {
            load_k(kb + 1); CP_COMMIT();
            load_v(kb + 1); CP_COMMIT();
        }

        float sacc[8][4];
        if (af) {
            // ---- S = Q K^T (tf32 k8; 8 k-steps x 8 key-tiles) ----
#pragma unroll
            for (int a = 0; a < 8; a++)
#pragma unroll
                for (int b = 0; b < 4; b++) sacc[a][b] = 0.0f;

#pragma unroll
            for (int ks = 0; ks < 8; ks++) {
                const int ch0 = ks * 2, ch1 = ks * 2 + 1;
                const u32 qr0 = QB + (u32)((w16 + g) * 256 + (t4 << 2));
                const u32 qr1 = QB + (u32)((w16 + g + 8) * 256 + (t4 << 2));
                u32 a0 = lds32(qr0 + (u32)((ch0 ^ gx) << 4));
                u32 a1 = lds32(qr1 + (u32)((ch0 ^ gx) << 4));
                u32 a2 = lds32(qr0 + (u32)((ch1 ^ gx) << 4));
                u32 a3 = lds32(qr1 + (u32)((ch1 ^ gx) << 4));
#pragma unroll
                for (int nt = 0; nt < 8; nt++) {
                    u32 kr = KB + (u32)((nt * 8 + g) * 256 + (t4 << 2));
                    u32 b0 = lds32(kr + (u32)((ch0 ^ gx) << 4));
                    u32 b1 = lds32(kr + (u32)((ch1 ^ gx) << 4));
                    mma1688t(sacc[nt], a0, a1, a2, a3, b0, b1);
                }
            }

            if (af == 1) {
#pragma unroll
                for (int nt = 0; nt < 8; nt++) {
                    float2 mk = *reinterpret_cast<const float2*>(
                        &mb[c0 + nt * 8 + t4 * 2]);
                    sacc[nt][0] += mk.x;
                    sacc[nt][1] += mk.y;
                    sacc[nt][2] += mk.x;
                    sacc[nt][3] += mk.y;
                }
            }

            // ---- online softmax (base-2 domain) ----
            float rmax0 = -1e30f, rmax1 = -1e30f;
#pragma unroll
            for (int nt = 0; nt < 8; nt++) {
                rmax0 = fmaxf(rmax0, fmaxf(sacc[nt][0], sacc[nt][1]));
                rmax1 = fmaxf(rmax1, fmaxf(sacc[nt][2], sacc[nt][3]));
            }
            rmax0 = fmaxf(rmax0, __shfl_xor_sync(0xffffffffu, rmax0, 1));
            rmax0 = fmaxf(rmax0, __shfl_xor_sync(0xffffffffu, rmax0, 2));
            rmax1 = fmaxf(rmax1, __shfl_xor_sync(0xffffffffu, rmax1, 1));
            rmax1 = fmaxf(rmax1, __shfl_xor_sync(0xffffffffu, rmax1, 2));
            float mn0 = fmaxf(mrow0, rmax0), mn1 = fmaxf(mrow1, rmax1);
            float corr0 = ex2(mrow0 - mn0), corr1 = ex2(mrow1 - mn1);
            mrow0 = mn0; mrow1 = mn1;
            float rs0 = 0.0f, rs1 = 0.0f;
#pragma unroll
            for (int nt = 0; nt < 8; nt++) {
                sacc[nt][0] = ex2(sacc[nt][0] - mn0);
                sacc[nt][1] = ex2(sacc[nt][1] - mn0);
                sacc[nt][2] = ex2(sacc[nt][2] - mn1);
                sacc[nt][3] = ex2(sacc[nt][3] - mn1);
                rs0 += sacc[nt][0] + sacc[nt][1];
                rs1 += sacc[nt][2] + sacc[nt][3];
            }
            rs0 += __shfl_xor_sync(0xffffffffu, rs0, 1);
            rs0 += __shfl_xor_sync(0xffffffffu, rs0, 2);
            rs1 += __shfl_xor_sync(0xffffffffu, rs1, 1);
            rs1 += __shfl_xor_sync(0xffffffffu, rs1, 2);
            lrow0 = lrow0 * corr0 + rs0;
            lrow1 = lrow1 * corr1 + rs1;
#pragma unroll
            for (int dt = 0; dt < 8; dt++) {
                oacc[dt][0] *= corr0; oacc[dt][1] *= corr0;
                oacc[dt][2] *= corr1; oacc[dt][3] *= corr1;
            }
        }

        // ---- wait for V(kb) ----
        if (more) { CP_WAIT(2); } else { CP_WAIT(0); }
        __syncthreads();

        if (af) {
            // ---- O += P V (tf32 k8; P redistributed C->A via shfl) ----
            const int srcA = (lane & ~3) | (t4 >> 1);
            const int srcB = srcA + 2;
            const bool odd = (t4 & 1) != 0;
            const u32 vcol = (u32)((g & 3) << 2);
            const int cb = g >> 2;
            const int x0 = t4 << 1;
            const int x1 = (t4 + 4) << 1;
#pragma unroll
            for (int kc = 0; kc < 8; kc++) {
                float v00 = __shfl_sync(0xffffffffu, sacc[kc][0], srcA);
                float v01 = __shfl_sync(0xffffffffu, sacc[kc][1], srcA);
                float v10 = __shfl_sync(0xffffffffu, sacc[kc][2], srcA);
                float v11 = __shfl_sync(0xffffffffu, sacc[kc][3], srcA);
                float v20 = __shfl_sync(0xffffffffu, sacc[kc][0], srcB);
                float v21 = __shfl_sync(0xffffffffu, sacc[kc][1], srcB);
                float v30 = __shfl_sync(0xffffffffu, sacc[kc][2], srcB);
                float v31 = __shfl_sync(0xffffffffu, sacc[kc][3], srcB);
                u32 a0 = cvt_tf32(odd ? v01 : v00);
                u32 a1 = cvt_tf32(odd ? v11 : v10);
                u32 a2 = cvt_tf32(odd ? v21 : v20);
                u32 a3 = cvt_tf32(odd ? v31 : v30);
                u32 vr0 = VB + (u32)((kc * 8 + t4) * 256) + vcol;
                u32 vr1 = VB + (u32)((kc * 8 + t4 + 4) * 256) + vcol;
#pragma unroll
                for (int dt = 0; dt < 8; dt++) {
                    int chn = (dt << 1) + cb;
                    u32 b0 = lds32(vr0 + (u32)((chn ^ x0) << 4));
                    u32 b1 = lds32(vr1 + (u32)((chn ^ x1) << 4));
                    mma1688t(oacc[dt], a0, a1, a2, a3, b0, b1);
                }
            }
        }
        // No end-of-tile barrier: next iteration's K-wait barrier precedes
        // any write into the buffer just read.
    }

    // ---- normalize + split-write [n, t, h*64 + d] as bf16 hi/lo ----
    float inv0 = 1.0f / lrow0, inv1 = 1.0f / lrow1;
#pragma unroll
    for (int dt = 0; dt < 8; dt++) {
        int col = h * DH + dt * 8 + t4 * 2;
        size_t r1 = (size_t)n * TT + q0 + wid * 16 + g;
        float a0 = oacc[dt][0] * inv0, a1 = oacc[dt][1] * inv0;
        float b0 = oacc[dt][2] * inv1, b1 = oacc[dt][3] * inv1;
        bf162 ha = __floats2bfloat162_rn(a0, a1);
        float2 fa = __bfloat1622float2(ha);
        bf162 la = __floats2bfloat162_rn(a0 - fa.x, a1 - fa.y);
        bf162 hbv = __floats2bfloat162_rn(b0, b1);
        float2 fb = __bfloat1622float2(hbv);
        bf162 lb = __floats2bfloat162_rn(b0 - fb.x, b1 - fb.y);
        *reinterpret_cast<bf162*>(&Aho[r1 * DM + col]) = ha;
        *reinterpret_cast<bf162*>(&Alo[r1 * DM + col]) = la;
        *reinterpret_cast<bf162*>(&Aho[(r1 + 8) * DM + col]) = hbv;
        *reinterpret_cast<bf162*>(&Alo[(r1 + 8) * DM + col]) = lb;
    }
}

// ---------------------------------------------------------------------------
// Launch
// ---------------------------------------------------------------------------
extern "C" void kernel_launch(void* const* d_in, const int* in_sizes, int n_in,
                              void* d_out, int out_size) {
    const float* x  = (const float*)d_in[0];
    const int*   mask = (const int*)d_in[1];
    const float* Wq = (const float*)d_in[2];
    const float* bq = (const float*)d_in[3];
    const float* Wk = (const float*)d_in[4];
    const float* bk = (const float*)d_in[5];
    const float* Wv = (const float*)d_in[6];
    const float* bv = (const float*)d_in[7];
    const float* Wo = (const float*)d_in[8];
    const float* bo = (const float*)d_in[9];
    float* out = (float*)d_out;

    bf16 *xh, *xl, *wqh, *wql, *wkh, *wkl, *wvh, *wvl, *woh, *wol, *ah, *al;
    float *qf, *kf, *vf, *mf;
    int *actg, *nag;
    cudaGetSymbolAddress((void**)&xh, g_xh);
    cudaGetSymbolAddress((void**)&xl, g_xl);
    cudaGetSymbolAddress((void**)&wqh, g_wqh);
    cudaGetSymbolAddress((void**)&wql, g_wql);
    cudaGetSymbolAddress((void**)&wkh, g_wkh);
    cudaGetSymbolAddress((void**)&wkl, g_wkl);
    cudaGetSymbolAddress((void**)&wvh, g_wvh);
    cudaGetSymbolAddress((void**)&wvl, g_wvl);
    cudaGetSymbolAddress((void**)&woh, g_woh);
    cudaGetSymbolAddress((void**)&wol, g_wol);
    cudaGetSymbolAddress((void**)&qf, g_qf);
    cudaGetSymbolAddress((void**)&kf, g_kf);
    cudaGetSymbolAddress((void**)&vf, g_vf);
    cudaGetSymbolAddress((void**)&ah, g_ah);
    cudaGetSymbolAddress((void**)&al, g_al);
    cudaGetSymbolAddress((void**)&mf, g_maskf);
    cudaGetSymbolAddress((void**)&actg, g_act);
    cudaGetSymbolAddress((void**)&nag, g_na);

    cudaFuncSetAttribute(gemm_qkv_kernel,
                         cudaFuncAttributeMaxDynamicSharedMemorySize, 98304);
    cudaFuncSetAttribute(gemm_out_kernel,
                         cudaFuncAttributeMaxDynamicSharedMemorySize, 73728);
    cudaFuncSetAttribute(flash_tf32_kernel,
                         cudaFuncAttributeMaxDynamicSharedMemorySize, 98304);

    prep_mask_kernel<<<NB, 64>>>(mask, mf, actg, nag);

    const int xn4 = MROWS * DM / 4;
    const int wn4 = DM * DM / 4;
    split_kernel<<<(xn4 + 255) / 256, 256>>>(x, xh, xl, xn4);
    split4w_kernel<<<(4 * wn4 + 255) / 256, 256>>>(
        Wq, Wk, Wv, Wo, wqh, wql, wkh, wkl, wvh, wvl, woh, wol, wn4);

    dim3 qkvgrid(MROWS / 128, DM / 128, 3);
    gemm_qkv_kernel<<<qkvgrid, 256, 98304>>>(
        xh, xl, wqh, wql, wkh, wkl, wvh, wvl, bq, bk, bv, qf, kf, vf);

    dim3 agrid(TT / 128, NH, NB);
    flash_tf32_kernel<<<agrid, 256, 98304>>>(qf, kf, vf, mf, actg, nag, ah, al);

    dim3 ogrid(MROWS / 64, DM / 128);
    gemm_out_kernel<<<ogrid, 256, 73728>>>(ah, al, woh, wol, bo, out);
}

// round 17
// speedup vs baseline: 1.7556x; 1.7556x over previous
#include <cuda_runtime.h>
#include <cuda_bf16.h>
#include <cuda_fp16.h>
#include <cstdint>

#define NB 2
#define TT 4096
#define DM 768
#define NH 12
#define DH 64
#define MROWS (NB * TT)   // 8192

typedef uint32_t u32;
typedef __nv_bfloat16 bf16;
typedef __nv_bfloat162 bf162;

#define QSCALE 0.18033688011112042f   // 0.125 * log2(e)

// ---------------------------------------------------------------------------
// Scratch in __device__ globals (allocation-free rule)
// ---------------------------------------------------------------------------
__device__ bf16 g_xh[(size_t)MROWS * DM];
__device__ bf16 g_xl[(size_t)MROWS * DM];
__device__ bf16 g_wqh[(size_t)DM * DM];
__device__ bf16 g_wql[(size_t)DM * DM];
__device__ bf16 g_wkh[(size_t)DM * DM];
__device__ bf16 g_wkl[(size_t)DM * DM];
__device__ bf16 g_wvh[(size_t)DM * DM];
__device__ bf16 g_wvl[(size_t)DM * DM];
__device__ bf16 g_woh[(size_t)DM * DM];
__device__ bf16 g_wol[(size_t)DM * DM];
__device__ __half g_q16[(size_t)MROWS * DM];
__device__ __half g_k16[(size_t)MROWS * DM];
__device__ __half g_v16[(size_t)MROWS * DM];
__device__ bf16 g_ah[(size_t)MROWS * DM];
__device__ bf16 g_al[(size_t)MROWS * DM];
__device__ float g_maskf[(size_t)NB * TT];   // t-domain: 0 or -1e30*log2e
__device__ int   g_act[NB * 64];             // 0=skip, 1=partial, 2=full
__device__ int   g_na[NB];                   // last active tile + 1

// ---------------------------------------------------------------------------
// Helpers
// ---------------------------------------------------------------------------
__device__ __forceinline__ u32 s2u(const void* p) {
    return (u32)__cvta_generic_to_shared(p);
}
__device__ __forceinline__ void cpa16(u32 dst, const void* src) {
    asm volatile("cp.async.cg.shared.global [%0], [%1], 16;" :: "r"(dst), "l"(src));
}
#define CP_COMMIT()  asm volatile("cp.async.commit_group;")
#define CP_WAIT(N)   asm volatile("cp.async.wait_group %0;" :: "n"(N))

__device__ __forceinline__ void ldsm4(u32& r0, u32& r1, u32& r2, u32& r3, u32 a) {
    asm volatile("ldmatrix.sync.aligned.m8n8.x4.shared.b16 {%0,%1,%2,%3},[%4];"
                 : "=r"(r0), "=r"(r1), "=r"(r2), "=r"(r3) : "r"(a));
}
__device__ __forceinline__ void ldsm4t(u32& r0, u32& r1, u32& r2, u32& r3, u32 a) {
    asm volatile("ldmatrix.sync.aligned.m8n8.x4.trans.shared.b16 {%0,%1,%2,%3},[%4];"
                 : "=r"(r0), "=r"(r1), "=r"(r2), "=r"(r3) : "r"(a));
}
__device__ __forceinline__ void mma16816(float* c, u32 a0, u32 a1, u32 a2, u32 a3,
                                         u32 b0, u32 b1) {
    asm volatile(
        "mma.sync.aligned.m16n8k16.row.col.f32.bf16.bf16.f32 "
        "{%0,%1,%2,%3},{%4,%5,%6,%7},{%8,%9},{%0,%1,%2,%3};"
        : "+f"(c[0]), "+f"(c[1]), "+f"(c[2]), "+f"(c[3])
        : "r"(a0), "r"(a1), "r"(a2), "r"(a3), "r"(b0), "r"(b1));
}
__device__ __forceinline__ void mma16816h(float* c, u32 a0, u32 a1, u32 a2, u32 a3,
                                          u32 b0, u32 b1) {
    asm volatile(
        "mma.sync.aligned.m16n8k16.row.col.f32.f16.f16.f32 "
        "{%0,%1,%2,%3},{%4,%5,%6,%7},{%8,%9},{%0,%1,%2,%3};"
        : "+f"(c[0]), "+f"(c[1]), "+f"(c[2]), "+f"(c[3])
        : "r"(a0), "r"(a1), "r"(a2), "r"(a3), "r"(b0), "r"(b1));
}
__device__ __forceinline__ u32 pkh(float lo, float hi) {
    __half2 t = __floats2half2_rn(lo, hi);
    return *reinterpret_cast<u32*>(&t);
}
__device__ __forceinline__ float ex2(float x) {
    float y;
    asm("ex2.approx.ftz.f32 %0, %1;" : "=f"(y) : "f"(x));
    return y;
}
// 16-bit tile swizzle (128B rows, 8 chunks)
__device__ __forceinline__ u32 swz(int row, int chunk) {
    return (u32)(row * 128 + ((chunk ^ (row & 7)) << 4));
}
__device__ __forceinline__ u32 frag_addr(u32 base, int r0, int c0, int lane) {
    return base + swz(r0 + (lane & 15), c0 + (lane >> 4));
}

// ---------------------------------------------------------------------------
// Mask prep
// ---------------------------------------------------------------------------
__global__ void prep_mask_kernel(const int* __restrict__ mask,
                                 float* __restrict__ out,
                                 int* __restrict__ actg, int* __restrict__ nag) {
    __shared__ int s_any[64];
    const int n = blockIdx.x, t = threadIdx.x;
    bool any = false, all = true;
#pragma unroll 8
    for (int j = 0; j < 64; j++) {
        int m = mask[n * TT + t * 64 + j];
        out[n * TT + t * 64 + j] = m ? -1.4426950e30f : 0.0f;
        any |= (m == 0);
        all &= (m == 0);
    }
    actg[n * 64 + t] = any ? (all ? 2 : 1) : 0;
    s_any[t] = any ? 1 : 0;
    __syncthreads();
    if (t == 0) {
        int na = 0;
        for (int j = 0; j < 64; j++)
            if (s_any[j]) na = j + 1;
        nag[n] = na;
    }
}

// ---------------------------------------------------------------------------
// fp32 -> bf16 hi/lo split
// ---------------------------------------------------------------------------
__device__ __forceinline__ void split4(float4 v, uint2& h, uint2& l) {
    bf162 h01 = __floats2bfloat162_rn(v.x, v.y);
    bf162 h23 = __floats2bfloat162_rn(v.z, v.w);
    float2 f01 = __bfloat1622float2(h01);
    float2 f23 = __bfloat1622float2(h23);
    bf162 l01 = __floats2bfloat162_rn(v.x - f01.x, v.y - f01.y);
    bf162 l23 = __floats2bfloat162_rn(v.z - f23.x, v.w - f23.y);
    h = make_uint2(*(u32*)&h01, *(u32*)&h23);
    l = make_uint2(*(u32*)&l01, *(u32*)&l23);
}

__global__ void split_kernel(const float* __restrict__ in, bf16* __restrict__ h,
                             bf16* __restrict__ l, int n4) {
    int i = blockIdx.x * blockDim.x + threadIdx.x;
    if (i >= n4) return;
    uint2 hh, ll;
    split4(reinterpret_cast<const float4*>(in)[i], hh, ll);
    reinterpret_cast<uint2*>(h)[i] = hh;
    reinterpret_cast<uint2*>(l)[i] = ll;
}

__global__ void split4w_kernel(const float* __restrict__ W0, const float* __restrict__ W1,
                               const float* __restrict__ W2, const float* __restrict__ W3,
                               bf16* __restrict__ h0, bf16* __restrict__ l0,
                               bf16* __restrict__ h1, bf16* __restrict__ l1,
                               bf16* __restrict__ h2, bf16* __restrict__ l2,
                               bf16* __restrict__ h3, bf16* __restrict__ l3, int n4) {
    int i = blockIdx.x * blockDim.x + threadIdx.x;
    int w = i / n4, j = i - w * n4;
    if (w >= 4) return;
    const float* in = (w == 0) ? W0 : (w == 1) ? W1 : (w == 2) ? W2 : W3;
    bf16* h = (w == 0) ? h0 : (w == 1) ? h1 : (w == 2) ? h2 : h3;
    bf16* l = (w == 0) ? l0 : (w == 1) ? l1 : (w == 2) ? l2 : l3;
    uint2 hh, ll;
    split4(reinterpret_cast<const float4*>(in)[j], hh, ll);
    reinterpret_cast<uint2*>(h)[j] = hh;
    reinterpret_cast<uint2*>(l)[j] = ll;
}

// ---------------------------------------------------------------------------
// 128x128 GEMM mainloop (bf16x3, 3-stage cp.async, BK=32). Used by qkv.
// ---------------------------------------------------------------------------
struct GemmCore {
    float acc[4][4][4];

    __device__ __forceinline__ void run(char* smraw, int tid, int lane,
                                        int wm, int wn, int row0, int col0,
                                        const bf16* Ah, const bf16* Al,
                                        const bf16* Bh, const bf16* Bl) {
#pragma unroll
        for (int a = 0; a < 4; a++)
#pragma unroll
            for (int b = 0; b < 4; b++)
#pragma unroll
                for (int c = 0; c < 4; c++) acc[a][b][c] = 0.0f;

        auto load_stage = [&](int s) {
            char* base = smraw + (s % 3) * 32768;
            u32 ab = s2u(base), bb = ab + 16384;
            int k0 = s * 32;
#pragma unroll
            for (int i = tid; i < 1024; i += 256) {
                int r = i >> 3, c = i & 7;
                const bf16* asrc = (c < 4)
                    ? &Ah[(size_t)(row0 + r) * DM + k0 + c * 8]
                    : &Al[(size_t)(row0 + r) * DM + k0 + (c - 4) * 8];
                cpa16(ab + swz(r, c), asrc);
                const bf16* bsrc = (c < 4)
                    ? &Bh[(size_t)(col0 + r) * DM + k0 + c * 8]
                    : &Bl[(size_t)(col0 + r) * DM + k0 + (c - 4) * 8];
                cpa16(bb + swz(r, c), bsrc);
            }
        };

        load_stage(0); CP_COMMIT();
        load_stage(1); CP_COMMIT();

        const int NS = DM / 32;  // 24
#pragma unroll 1
        for (int s = 0; s < NS; s++) {
            if (s + 1 < NS) { CP_WAIT(1); } else { CP_WAIT(0); }
            __syncthreads();

            u32 ab = s2u(smraw + (s % 3) * 32768), bb = ab + 16384;
#pragma unroll
            for (int kt = 0; kt < 2; kt++) {
                const int ch = 2 * kt, cl = 4 + 2 * kt;
                u32 bhf[4][2], blf[4][2];
#pragma unroll
                for (int half = 0; half < 2; half++) {
                    u32 r0, r1, r2, r3;
                    ldsm4(r0, r1, r2, r3, frag_addr(bb, wn * 32 + half * 16, ch, lane));
                    bhf[2 * half][0] = r0; bhf[2 * half + 1][0] = r1;
                    bhf[2 * half][1] = r2; bhf[2 * half + 1][1] = r3;
                    ldsm4(r0, r1, r2, r3, frag_addr(bb, wn * 32 + half * 16, cl, lane));
                    blf[2 * half][0] = r0; blf[2 * half + 1][0] = r1;
                    blf[2 * half][1] = r2; blf[2 * half + 1][1] = r3;
                }
#pragma unroll
                for (int mt = 0; mt < 4; mt++) {
                    u32 ah4[4], al4[4];
                    ldsm4(ah4[0], ah4[1], ah4[2], ah4[3],
                          frag_addr(ab, wm * 64 + mt * 16, ch, lane));
                    ldsm4(al4[0], al4[1], al4[2], al4[3],
                          frag_addr(ab, wm * 64 + mt * 16, cl, lane));
#pragma unroll
                    for (int nt = 0; nt < 4; nt++) {
                        mma16816(acc[mt][nt], ah4[0], ah4[1], ah4[2], ah4[3],
                                 bhf[nt][0], bhf[nt][1]);
                        mma16816(acc[mt][nt], ah4[0], ah4[1], ah4[2], ah4[3],
                                 blf[nt][0], blf[nt][1]);
                        mma16816(acc[mt][nt], al4[0], al4[1], al4[2], al4[3],
                                 bhf[nt][0], bhf[nt][1]);
                    }
                }
            }
            if (s + 2 < NS) { load_stage(s + 2); CP_COMMIT(); }
        }
    }
};

// ---------------------------------------------------------------------------
// Fused Q/K/V projection: epilogue emits fp16, head-split [n,h,t,dh].
// ---------------------------------------------------------------------------
__global__ __launch_bounds__(256, 2)
void gemm_qkv_kernel(const bf16* __restrict__ Xh, const bf16* __restrict__ Xl,
                     const bf16* __restrict__ Wqh, const bf16* __restrict__ Wql,
                     const bf16* __restrict__ Wkh, const bf16* __restrict__ Wkl,
                     const bf16* __restrict__ Wvh, const bf16* __restrict__ Wvl,
                     const float* __restrict__ bq, const float* __restrict__ bk,
                     const float* __restrict__ bv,
                     __half* __restrict__ Q16, __half* __restrict__ K16,
                     __half* __restrict__ V16) {
    extern __shared__ char smraw[];
    const int tid = threadIdx.x, lane = tid & 31, wid = tid >> 5;
    const int wm = wid >> 2, wn = wid & 3;
    const int row0 = blockIdx.x * 128, col0 = blockIdx.y * 128;
    const int w = blockIdx.z;

    const bf16* Bh = (w == 0) ? Wqh : (w == 1) ? Wkh : Wvh;
    const bf16* Bl = (w == 0) ? Wql : (w == 1) ? Wkl : Wvl;
    const float* bias = (w == 0) ? bq : (w == 1) ? bk : bv;
    __half* Of = (w == 0) ? Q16 : (w == 1) ? K16 : V16;
    const float cscale = (w == 0) ? QSCALE : 1.0f;

    GemmCore core;
    core.run(smraw, tid, lane, wm, wn, row0, col0, Xh, Xl, Bh, Bl);

    const int g = lane >> 2, t4 = lane & 3;
#pragma unroll
    for (int mt = 0; mt < 4; mt++)
#pragma unroll
        for (int nt = 0; nt < 4; nt++) {
            int col = col0 + wn * 32 + nt * 8 + t4 * 2;
            float bv0 = bias[col], bv1 = bias[col + 1];
#pragma unroll
            for (int half = 0; half < 2; half++) {
                int row = row0 + wm * 64 + mt * 16 + g + half * 8;
                float c0 = (core.acc[mt][nt][2 * half] + bv0) * cscale;
                float c1 = (core.acc[mt][nt][2 * half + 1] + bv1) * cscale;
                int n = row >> 12, t = row & (TT - 1);
                int h = col >> 6, d = col & 63;
                size_t idx = (((size_t)(n * NH + h)) * TT + t) * DH + d;
                __half2 hv = __floats2half2_rn(c0, c1);
                *reinterpret_cast<__half2*>(&Of[idx]) = hv;
            }
        }
}

// ---------------------------------------------------------------------------
// Output projection: 64x128 tiles, bf16x3 (unchanged from R15).
// ---------------------------------------------------------------------------
__global__ __launch_bounds__(256, 2)
void gemm_out_kernel(const bf16* __restrict__ Ahg, const bf16* __restrict__ Alg,
                     const bf16* __restrict__ Bh, const bf16* __restrict__ Bl,
                     const float* __restrict__ bias, float* __restrict__ C) {
    extern __shared__ char smraw[];
    const int tid = threadIdx.x, lane = tid & 31, wid = tid >> 5;
    const int wm = wid >> 2, wn = wid & 3;
    const int row0 = blockIdx.x * 64, col0 = blockIdx.y * 128;

    float acc[2][4][4];
#pragma unroll
    for (int a = 0; a < 2; a++)
#pragma unroll
        for (int b = 0; b < 4; b++)
#pragma unroll
            for (int c = 0; c < 4; c++) acc[a][b][c] = 0.0f;

    auto load_stage = [&](int s) {
        char* base = smraw + (s % 3) * 24576;
        u32 ab = s2u(base), bb = ab + 8192;
        int k0 = s * 32;
#pragma unroll
        for (int i = tid; i < 512; i += 256) {
            int r = i >> 3, c = i & 7;
            const bf16* asrc = (c < 4)
                ? &Ahg[(size_t)(row0 + r) * DM + k0 + c * 8]
                : &Alg[(size_t)(row0 + r) * DM + k0 + (c - 4) * 8];
            cpa16(ab + swz(r, c), asrc);
        }
#pragma unroll
        for (int i = tid; i < 1024; i += 256) {
            int r = i >> 3, c = i & 7;
            const bf16* bsrc = (c < 4)
                ? &Bh[(size_t)(col0 + r) * DM + k0 + c * 8]
                : &Bl[(size_t)(col0 + r) * DM + k0 + (c - 4) * 8];
            cpa16(bb + swz(r, c), bsrc);
        }
    };

    load_stage(0); CP_COMMIT();
    load_stage(1); CP_COMMIT();

    const int NS = DM / 32;  // 24
#pragma unroll 1
    for (int s = 0; s < NS; s++) {
        if (s + 1 < NS) { CP_WAIT(1); } else { CP_WAIT(0); }
        __syncthreads();

        u32 ab = s2u(smraw + (s % 3) * 24576), bb = ab + 8192;
#pragma unroll
        for (int kt = 0; kt < 2; kt++) {
            const int ch = 2 * kt, cl = 4 + 2 * kt;
            u32 bhf[4][2], blf[4][2];
#pragma unroll
            for (int half = 0; half < 2; half++) {
                u32 r0, r1, r2, r3;
                ldsm4(r0, r1, r2, r3, frag_addr(bb, wn * 32 + half * 16, ch, lane));
                bhf[2 * half][0] = r0; bhf[2 * half + 1][0] = r1;
                bhf[2 * half][1] = r2; bhf[2 * half + 1][1] = r3;
                ldsm4(r0, r1, r2, r3, frag_addr(bb, wn * 32 + half * 16, cl, lane));
                blf[2 * half][0] = r0; blf[2 * half + 1][0] = r1;
                blf[2 * half][1] = r2; blf[2 * half + 1][1] = r3;
            }
#pragma unroll
            for (int mt = 0; mt < 2; mt++) {
                u32 ah4[4], al4[4];
                ldsm4(ah4[0], ah4[1], ah4[2], ah4[3],
                      frag_addr(ab, wm * 32 + mt * 16, ch, lane));
                ldsm4(al4[0], al4[1], al4[2], al4[3],
                      frag_addr(ab, wm * 32 + mt * 16, cl, lane));
#pragma unroll
                for (int nt = 0; nt < 4; nt++) {
                    mma16816(acc[mt][nt], ah4[0], ah4[1], ah4[2], ah4[3],
                             bhf[nt][0], bhf[nt][1]);
                    mma16816(acc[mt][nt], ah4[0], ah4[1], ah4[2], ah4[3],
                             blf[nt][0], blf[nt][1]);
                    mma16816(acc[mt][nt], al4[0], al4[1], al4[2], al4[3],
                             bhf[nt][0], bhf[nt][1]);
                }
            }
        }
        if (s + 2 < NS) { load_stage(s + 2); CP_COMMIT(); }
    }

    const int g = lane >> 2, t4 = lane & 3;
#pragma unroll
    for (int mt = 0; mt < 2; mt++)
#pragma unroll
        for (int nt = 0; nt < 4; nt++) {
            int col = col0 + wn * 32 + nt * 8 + t4 * 2;
            float bv0 = bias[col], bv1 = bias[col + 1];
#pragma unroll
            for (int half = 0; half < 2; half++) {
                int row = row0 + wm * 32 + mt * 16 + g + half * 8;
                float c0 = acc[mt][nt][2 * half] + bv0;
                float c1 = acc[mt][nt][2 * half + 1] + bv1;
                *reinterpret_cast<float2*>(&C[(size_t)row * DM + col]) =
                    make_float2(c0, c1);
            }
        }
}

// ---------------------------------------------------------------------------
// P fragment conversion (fp32 sacc pair -> fp16 A-fragments, single pass)
// ---------------------------------------------------------------------------
struct PFragH { u32 h[4]; };

__device__ __forceinline__ PFragH cvt_pfrag_h(const float s0[4], const float s1[4]) {
    PFragH p;
    p.h[0] = pkh(s0[0], s0[1]);
    p.h[1] = pkh(s0[2], s0[3]);
    p.h[2] = pkh(s1[0], s1[1]);
    p.h[3] = pkh(s1[2], s1[3]);
    return p;
}

// ---------------------------------------------------------------------------
// Flash attention, fp16 single-pass MMAs (S and PV). Structure identical to
// the proven R15 pipeline: split K/V waits, deferred next-tile loads (2
// barriers/tile), pipelined P conversion, unconditional rescale.
// smem: Q 16KB | 2 KV stages of (K 8KB + V 8KB) = 48KB total.
// ---------------------------------------------------------------------------
__global__ __launch_bounds__(256, 2)
void flash_fp16_kernel(const __half* __restrict__ Qg, const __half* __restrict__ Kg,
                       const __half* __restrict__ Vg,
                       const float* __restrict__ mbf,
                       const int* __restrict__ actg, const int* __restrict__ nag,
                       bf16* __restrict__ Aho, bf16* __restrict__ Alo) {
    extern __shared__ char smraw[];
    __shared__ int act_s[64];
    const u32 QB = s2u(smraw);

    const int n = blockIdx.z, h = blockIdx.y;
    const int q0 = blockIdx.x * 128;
    const size_t hb = ((size_t)(n * NH + h)) * TT * DH;
    const float* mb = mbf + (size_t)n * TT;

    const int tid = threadIdx.x, lane = tid & 31, wid = tid >> 5;
    const int g = lane >> 2, t4 = lane & 3;

    // Stage Q fp16 (own commit group; drains with the first K wait)
#pragma unroll
    for (int i = tid; i < 1024; i += 256) {
        int r = i >> 3, c = i & 7;
        cpa16(QB + swz(r, c), Qg + hb + (size_t)(q0 + r) * DH + c * 8);
    }
    CP_COMMIT();

    if (tid < 64) act_s[tid] = actg[n * 64 + tid];
    const int na = nag[n];
    __syncthreads();

    auto load_k = [&](int kb) {
        u32 base = s2u(smraw + 16384 + (kb & 1) * 16384);
        int c0 = kb * 64;
#pragma unroll
        for (int i = tid; i < 512; i += 256) {
            int r = i >> 3, c = i & 7;
            cpa16(base + swz(r, c), Kg + hb + (size_t)(c0 + r) * DH + c * 8);
        }
    };
    auto load_v = [&](int kb) {
        u32 base = s2u(smraw + 16384 + (kb & 1) * 16384) + 8192;
        int c0 = kb * 64;
#pragma unroll
        for (int i = tid; i < 512; i += 256) {
            int r = i >> 3, c = i & 7;
            cpa16(base + swz(r, c), Vg + hb + (size_t)(c0 + r) * DH + c * 8);
        }
    };

    float oacc[8][4];
#pragma unroll
    for (int a = 0; a < 8; a++)
#pragma unroll
        for (int b = 0; b < 4; b++) oacc[a][b] = 0.0f;
    float mrow0 = -1e30f, mrow1 = -1e30f, lrow0 = 0.0f, lrow1 = 0.0f;

    if (na > 0) {
        load_k(0); CP_COMMIT();
        load_v(0); CP_COMMIT();
    }

#pragma unroll 1
    for (int kb = 0; kb < na; kb++) {
        const bool more = (kb + 1 < na);
        const int af = act_s[kb];
        const int c0 = kb * 64;
        const u32 KB = s2u(smraw + 16384 + (kb & 1) * 16384);
        const u32 VB = KB + 8192;

        // ---- wait for K(kb); barrier also guards buffer reuse ----
        CP_WAIT(1);
        __syncthreads();

        // ---- issue next tile's loads ----
        if (more) {
            load_k(kb + 1); CP_COMMIT();
            load_v(kb + 1); CP_COMMIT();
        }

        float sacc[8][4];
        if (af) {
            // ---- S = Q K^T (fp16 single pass: 4 kt x 8 = 32 MMAs) ----
#pragma unroll
            for (int a = 0; a < 8; a++)
#pragma unroll
                for (int b = 0; b < 4; b++) sacc[a][b] = 0.0f;

#pragma unroll
            for (int kt = 0; kt < 4; kt++) {
                u32 q4[4];
                ldsm4(q4[0], q4[1], q4[2], q4[3],
                      frag_addr(QB, wid * 16, kt * 2, lane));
#pragma unroll
                for (int hf = 0; hf < 4; hf++) {
                    u32 k0r, k1r, k2r, k3r;
                    ldsm4(k0r, k1r, k2r, k3r,
                          frag_addr(KB, hf * 16, kt * 2, lane));
                    mma16816h(sacc[2 * hf],     q4[0], q4[1], q4[2], q4[3], k0r, k2r);
                    mma16816h(sacc[2 * hf + 1], q4[0], q4[1], q4[2], q4[3], k1r, k3r);
                }
            }

            if (af == 1) {
#pragma unroll
                for (int nt = 0; nt < 8; nt++) {
                    float2 mk = *reinterpret_cast<const float2*>(
                        &mb[c0 + nt * 8 + t4 * 2]);
                    sacc[nt][0] += mk.x;
                    sacc[nt][1] += mk.y;
                    sacc[nt][2] += mk.x;
                    sacc[nt][3] += mk.y;
                }
            }

            // ---- online softmax (base-2 domain) ----
            float rmax0 = -1e30f, rmax1 = -1e30f;
#pragma unroll
            for (int nt = 0; nt < 8; nt++) {
                rmax0 = fmaxf(rmax0, fmaxf(sacc[nt][0], sacc[nt][1]));
                rmax1 = fmaxf(rmax1, fmaxf(sacc[nt][2], sacc[nt][3]));
            }
            rmax0 = fmaxf(rmax0, __shfl_xor_sync(0xffffffffu, rmax0, 1));
            rmax0 = fmaxf(rmax0, __shfl_xor_sync(0xffffffffu, rmax0, 2));
            rmax1 = fmaxf(rmax1, __shfl_xor_sync(0xffffffffu, rmax1, 1));
            rmax1 = fmaxf(rmax1, __shfl_xor_sync(0xffffffffu, rmax1, 2));
            float mn0 = fmaxf(mrow0, rmax0), mn1 = fmaxf(mrow1, rmax1);
            float corr0 = ex2(mrow0 - mn0), corr1 = ex2(mrow1 - mn1);
            mrow0 = mn0; mrow1 = mn1;
            float rs0 = 0.0f, rs1 = 0.0f;
#pragma unroll
            for (int nt = 0; nt < 8; nt++) {
                sacc[nt][0] = ex2(sacc[nt][0] - mn0);
                sacc[nt][1] = ex2(sacc[nt][1] - mn0);
                sacc[nt][2] = ex2(sacc[nt][2] - mn1);
                sacc[nt][3] = ex2(sacc[nt][3] - mn1);
                rs0 += sacc[nt][0] + sacc[nt][1];
                rs1 += sacc[nt][2] + sacc[nt][3];
            }
            rs0 += __shfl_xor_sync(0xffffffffu, rs0, 1);
            rs0 += __shfl_xor_sync(0xffffffffu, rs0, 2);
            rs1 += __shfl_xor_sync(0xffffffffu, rs1, 1);
            rs1 += __shfl_xor_sync(0xffffffffu, rs1, 2);
            lrow0 = lrow0 * corr0 + rs0;
            lrow1 = lrow1 * corr1 + rs1;
            // Unconditional rescale: corr == 1.0 exactly when max unchanged.
#pragma unroll
            for (int dt = 0; dt < 8; dt++) {
                oacc[dt][0] *= corr0; oacc[dt][1] *= corr0;
                oacc[dt][2] *= corr1; oacc[dt][3] *= corr1;
            }
        }

        // ---- convert j=0's P fragments BEFORE the V wait ----
        PFragH pa;
        if (af) pa = cvt_pfrag_h(sacc[0], sacc[1]);

        // ---- wait for V(kb) ----
        if (more) { CP_WAIT(2); } else { CP_WAIT(0); }
        __syncthreads();

        if (af) {
            // ---- O += P V (fp16 single pass: 4 j x 8 = 32 MMAs) ----
#pragma unroll
            for (int j = 0; j < 4; j++) {
                PFragH pnext;
                if (j < 3) pnext = cvt_pfrag_h(sacc[2 * j + 2], sacc[2 * j + 3]);
#pragma unroll
                for (int c = 0; c < 4; c++) {
                    u32 v0, v1, v2, v3;
                    ldsm4t(v0, v1, v2, v3, frag_addr(VB, j * 16, c * 2, lane));
                    mma16816h(oacc[2 * c],     pa.h[0], pa.h[1], pa.h[2], pa.h[3], v0, v1);
                    mma16816h(oacc[2 * c + 1], pa.h[0], pa.h[1], pa.h[2], pa.h[3], v2, v3);
                }
                if (j < 3) pa = pnext;
            }
        }
        // No end-of-tile barrier: next iteration's K-wait barrier precedes
        // any write into the buffer just read.
    }

    // ---- normalize + split-write [n, t, h*64 + d] as bf16 hi/lo ----
    float inv0 = 1.0f / lrow0, inv1 = 1.0f / lrow1;
#pragma unroll
    for (int dt = 0; dt < 8; dt++) {
        int col = h * DH + dt * 8 + t4 * 2;
        size_t r1 = (size_t)n * TT + q0 + wid * 16 + g;
        float a0 = oacc[dt][0] * inv0, a1 = oacc[dt][1] * inv0;
        float b0 = oacc[dt][2] * inv1, b1 = oacc[dt][3] * inv1;
        bf162 ha = __floats2bfloat162_rn(a0, a1);
        float2 fa = __bfloat1622float2(ha);
        bf162 la = __floats2bfloat162_rn(a0 - fa.x, a1 - fa.y);
        bf162 hbv = __floats2bfloat162_rn(b0, b1);
        float2 fb = __bfloat1622float2(hbv);
        bf162 lb = __floats2bfloat162_rn(b0 - fb.x, b1 - fb.y);
        *reinterpret_cast<bf162*>(&Aho[r1 * DM + col]) = ha;
        *reinterpret_cast<bf162*>(&Alo[r1 * DM + col]) = la;
        *reinterpret_cast<bf162*>(&Aho[(r1 + 8) * DM + col]) = hbv;
        *reinterpret_cast<bf162*>(&Alo[(r1 + 8) * DM + col]) = lb;
    }
}

// ---------------------------------------------------------------------------
// Launch
// ---------------------------------------------------------------------------
extern "C" void kernel_launch(void* const* d_in, const int* in_sizes, int n_in,
                              void* d_out, int out_size) {
    const float* x  = (const float*)d_in[0];
    const int*   mask = (const int*)d_in[1];
    const float* Wq = (const float*)d_in[2];
    const float* bq = (const float*)d_in[3];
    const float* Wk = (const float*)d_in[4];
    const float* bk = (const float*)d_in[5];
    const float* Wv = (const float*)d_in[6];
    const float* bv = (const float*)d_in[7];
    const float* Wo = (const float*)d_in[8];
    const float* bo = (const float*)d_in[9];
    float* out = (float*)d_out;

    bf16 *xh, *xl, *wqh, *wql, *wkh, *wkl, *wvh, *wvl, *woh, *wol, *ah, *al;
    __half *q16, *k16, *v16;
    float *mf;
    int *actg, *nag;
    cudaGetSymbolAddress((void**)&xh, g_xh);
    cudaGetSymbolAddress((void**)&xl, g_xl);
    cudaGetSymbolAddress((void**)&wqh, g_wqh);
    cudaGetSymbolAddress((void**)&wql, g_wql);
    cudaGetSymbolAddress((void**)&wkh, g_wkh);
    cudaGetSymbolAddress((void**)&wkl, g_wkl);
    cudaGetSymbolAddress((void**)&wvh, g_wvh);
    cudaGetSymbolAddress((void**)&wvl, g_wvl);
    cudaGetSymbolAddress((void**)&woh, g_woh);
    cudaGetSymbolAddress((void**)&wol, g_wol);
    cudaGetSymbolAddress((void**)&q16, g_q16);
    cudaGetSymbolAddress((void**)&k16, g_k16);
    cudaGetSymbolAddress((void**)&v16, g_v16);
    cudaGetSymbolAddress((void**)&ah, g_ah);
    cudaGetSymbolAddress((void**)&al, g_al);
    cudaGetSymbolAddress((void**)&mf, g_maskf);
    cudaGetSymbolAddress((void**)&actg, g_act);
    cudaGetSymbolAddress((void**)&nag, g_na);

    cudaFuncSetAttribute(gemm_qkv_kernel,
                         cudaFuncAttributeMaxDynamicSharedMemorySize, 98304);
    cudaFuncSetAttribute(gemm_out_kernel,
                         cudaFuncAttributeMaxDynamicSharedMemorySize, 73728);
    cudaFuncSetAttribute(flash_fp16_kernel,
                         cudaFuncAttributeMaxDynamicSharedMemorySize, 49152);

    prep_mask_kernel<<<NB, 64>>>(mask, mf, actg, nag);

    const int xn4 = MROWS * DM / 4;
    const int wn4 = DM * DM / 4;
    split_kernel<<<(xn4 + 255) / 256, 256>>>(x, xh, xl, xn4);
    split4w_kernel<<<(4 * wn4 + 255) / 256, 256>>>(
        Wq, Wk, Wv, Wo, wqh, wql, wkh, wkl, wvh, wvl, woh, wol, wn4);

    dim3 qkvgrid(MROWS / 128, DM / 128, 3);
    gemm_qkv_kernel<<<qkvgrid, 256, 98304>>>(
        xh, xl, wqh, wql, wkh, wkl, wvh, wvl, bq, bk, bv, q16, k16, v16);

    dim3 agrid(TT / 128, NH, NB);
    flash_fp16_kernel<<<agrid, 256, 49152>>>(q16, k16, v16, mf, actg, nag, ah, al);

    dim3 ogrid(MROWS / 64, DM / 128);
    gemm_out_kernel<<<ogrid, 256, 73728>>>(ah, al, woh, wol, bo, out);
}